// round 5
// baseline (speedup 1.0000x reference)
#include <cuda_runtime.h>
#include <math.h>

// Problem constants
#define Bq  4
#define Hh  64
#define Ww  64
#define Cc  128
#define NHh 4
#define Kk  7
#define HDd 32
#define MLPD 512
#define NTOK (Bq*Hh*Ww)   // 16384

// Scratch (device globals — no allocation allowed in kernel_launch)
__device__ float g_qn    [NTOK*Cc];
__device__ float g_kvn   [NTOK*Cc];
__device__ float g_q     [NTOK*Cc];
__device__ float g_kv    [NTOK*2*Cc];
__device__ float g_attn  [NTOK*Cc];
__device__ float g_x     [NTOK*Cc];
__device__ float g_hln   [NTOK*Cc];
__device__ float g_hidden[NTOK*MLPD];

// ---------------------------------------------------------------------------
// LayerNorm: one warp per token (C=128, lane handles 4 contiguous floats)
// ---------------------------------------------------------------------------
__global__ void ln_kernel(const float* __restrict__ in,
                          const float* __restrict__ g,
                          const float* __restrict__ b,
                          float* __restrict__ out, int ntok)
{
    int warp = (blockIdx.x * blockDim.x + threadIdx.x) >> 5;
    int lane = threadIdx.x & 31;
    if (warp >= ntok) return;

    const float4 v = *(const float4*)&in[(size_t)warp*Cc + lane*4];
    float s  = v.x + v.y + v.z + v.w;
    float sq = v.x*v.x + v.y*v.y + v.z*v.z + v.w*v.w;
    #pragma unroll
    for (int off = 16; off; off >>= 1) {
        s  += __shfl_xor_sync(0xffffffff, s,  off);
        sq += __shfl_xor_sync(0xffffffff, sq, off);
    }
    float mean = s * (1.0f/Cc);
    float var  = sq * (1.0f/Cc) - mean*mean;
    float inv  = rsqrtf(var + 1e-5f);

    const float4 gv = *(const float4*)&g[lane*4];
    const float4 bv = *(const float4*)&b[lane*4];
    float4 o;
    o.x = (v.x - mean)*inv*gv.x + bv.x;
    o.y = (v.y - mean)*inv*gv.y + bv.y;
    o.z = (v.z - mean)*inv*gv.z + bv.z;
    o.w = (v.w - mean)*inv*gv.w + bv.w;
    *(float4*)&out[(size_t)warp*Cc + lane*4] = o;
}

// ---------------------------------------------------------------------------
// TF32 tensor-core GEMM: C = epilogue(A[MxK] @ W[KxN] + bias)
//   MODE 0: +bias
//   MODE 1: (+bias) * scale
//   MODE 2: gelu(+bias)  (exact erf gelu)
//   MODE 3: +bias + residual[MxN]
// CTA 128x128, BK=16 double buffered, 256 threads, 8 warps (4m x 2n),
// warp tile 32x64 via mma.sync m16n8k8 tf32.
// SMEM layouts: As[k][m] pitch 136, Bs[k][n] pitch 136 (conflict-free frags).
// Requires M%128==0, N%128==0, K%16==0.
// ---------------------------------------------------------------------------
#define GP 136   // smem pitch (floats)

__device__ __forceinline__ float f2tf32(float x) {
    float r;
    asm("cvt.rna.tf32.f32 %0, %1;" : "=f"(r) : "f"(x));
    return r;
}

template <int MODE>
__global__ __launch_bounds__(256)
void gemm_tc(const float* __restrict__ A,
             const float* __restrict__ W,
             const float* __restrict__ bias,
             const float* __restrict__ res,
             float* __restrict__ C,
             int M, int N, int K, float scale)
{
    __shared__ float As[2][16*GP];
    __shared__ float Bs[2][16*GP];

    const int tid  = threadIdx.x;
    const int bm   = blockIdx.y * 128;
    const int bn   = blockIdx.x * 128;
    const int warp = tid >> 5;
    const int lane = tid & 31;
    const int g    = lane >> 2;     // group id (0..7)
    const int t    = lane & 3;      // thread in group (0..3)
    const int warpM = warp >> 1;    // 0..3
    const int warpN = warp & 1;     // 0..1
    const int m_base = warpM * 32;
    const int n_base = warpN * 64;

    // global load mapping
    const int ar = tid >> 1;              // A row 0..127
    const int ac = (tid & 1) * 8;         // A k offset 0/8
    const int wr = tid >> 4;              // W k row 0..15
    const int wc = (tid & 15) * 8;        // W n offset 0..120

    const float* Ag = A + (size_t)(bm + ar) * K + ac;
    const float* Wg = W + (size_t)wr * N + bn + wc;

    float acc[2][8][4];
    #pragma unroll
    for (int mt = 0; mt < 2; mt++)
        #pragma unroll
        for (int nt = 0; nt < 8; nt++)
            #pragma unroll
            for (int e = 0; e < 4; e++) acc[mt][nt][e] = 0.0f;

    const int ntile = K / 16;

    float4 av0 = *(const float4*)(Ag);
    float4 av1 = *(const float4*)(Ag + 4);
    float4 bv0 = *(const float4*)(Wg);
    float4 bv1 = *(const float4*)(Wg + 4);

    // stage tile 0
    {
        float* as = As[0];
        as[(ac+0)*GP + ar] = f2tf32(av0.x);
        as[(ac+1)*GP + ar] = f2tf32(av0.y);
        as[(ac+2)*GP + ar] = f2tf32(av0.z);
        as[(ac+3)*GP + ar] = f2tf32(av0.w);
        as[(ac+4)*GP + ar] = f2tf32(av1.x);
        as[(ac+5)*GP + ar] = f2tf32(av1.y);
        as[(ac+6)*GP + ar] = f2tf32(av1.z);
        as[(ac+7)*GP + ar] = f2tf32(av1.w);
        float* bs = Bs[0] + wr*GP + wc;
        float4 c0 = make_float4(f2tf32(bv0.x), f2tf32(bv0.y), f2tf32(bv0.z), f2tf32(bv0.w));
        float4 c1 = make_float4(f2tf32(bv1.x), f2tf32(bv1.y), f2tf32(bv1.z), f2tf32(bv1.w));
        *(float4*)(bs)     = c0;
        *(float4*)(bs + 4) = c1;
    }
    __syncthreads();

    for (int kt = 0; kt < ntile; kt++) {
        const int cur = kt & 1;
        if (kt + 1 < ntile) {
            const float* Ap = Ag + (kt + 1) * 16;
            const float* Wp = Wg + (size_t)(kt + 1) * 16 * N;
            av0 = *(const float4*)(Ap);
            av1 = *(const float4*)(Ap + 4);
            bv0 = *(const float4*)(Wp);
            bv1 = *(const float4*)(Wp + 4);
        }

        const float* as = As[cur];
        const float* bs = Bs[cur];
        #pragma unroll
        for (int kk = 0; kk < 16; kk += 8) {
            unsigned af[2][4], bf[8][2];
            #pragma unroll
            for (int mt = 0; mt < 2; mt++) {
                int m0 = m_base + mt*16 + g;
                af[mt][0] = __float_as_uint(as[(kk+t  )*GP + m0    ]);
                af[mt][1] = __float_as_uint(as[(kk+t  )*GP + m0 + 8]);
                af[mt][2] = __float_as_uint(as[(kk+t+4)*GP + m0    ]);
                af[mt][3] = __float_as_uint(as[(kk+t+4)*GP + m0 + 8]);
            }
            #pragma unroll
            for (int nt = 0; nt < 8; nt++) {
                int n0 = n_base + nt*8 + g;
                bf[nt][0] = __float_as_uint(bs[(kk+t  )*GP + n0]);
                bf[nt][1] = __float_as_uint(bs[(kk+t+4)*GP + n0]);
            }
            #pragma unroll
            for (int mt = 0; mt < 2; mt++)
                #pragma unroll
                for (int nt = 0; nt < 8; nt++)
                    asm volatile(
                        "mma.sync.aligned.m16n8k8.row.col.f32.tf32.tf32.f32 "
                        "{%0,%1,%2,%3}, {%4,%5,%6,%7}, {%8,%9}, {%0,%1,%2,%3};"
                        : "+f"(acc[mt][nt][0]), "+f"(acc[mt][nt][1]),
                          "+f"(acc[mt][nt][2]), "+f"(acc[mt][nt][3])
                        : "r"(af[mt][0]), "r"(af[mt][1]), "r"(af[mt][2]), "r"(af[mt][3]),
                          "r"(bf[nt][0]), "r"(bf[nt][1]));
        }

        if (kt + 1 < ntile) {
            const int nxt = cur ^ 1;
            float* asn = As[nxt];
            asn[(ac+0)*GP + ar] = f2tf32(av0.x);
            asn[(ac+1)*GP + ar] = f2tf32(av0.y);
            asn[(ac+2)*GP + ar] = f2tf32(av0.z);
            asn[(ac+3)*GP + ar] = f2tf32(av0.w);
            asn[(ac+4)*GP + ar] = f2tf32(av1.x);
            asn[(ac+5)*GP + ar] = f2tf32(av1.y);
            asn[(ac+6)*GP + ar] = f2tf32(av1.z);
            asn[(ac+7)*GP + ar] = f2tf32(av1.w);
            float* bsn = Bs[nxt] + wr*GP + wc;
            float4 c0 = make_float4(f2tf32(bv0.x), f2tf32(bv0.y), f2tf32(bv0.z), f2tf32(bv0.w));
            float4 c1 = make_float4(f2tf32(bv1.x), f2tf32(bv1.y), f2tf32(bv1.z), f2tf32(bv1.w));
            *(float4*)(bsn)     = c0;
            *(float4*)(bsn + 4) = c1;
        }
        __syncthreads();
    }

    // epilogue: thread owns rows (g, g+8) per m-tile, cols (2t, 2t+1) per n-tile
    #pragma unroll
    for (int mt = 0; mt < 2; mt++) {
        int row0 = bm + m_base + mt*16 + g;
        int row1 = row0 + 8;
        #pragma unroll
        for (int nt = 0; nt < 8; nt++) {
            int col = bn + n_base + nt*8 + 2*t;
            float b0 = bias[col], b1 = bias[col+1];
            float v00 = acc[mt][nt][0] + b0;
            float v01 = acc[mt][nt][1] + b1;
            float v10 = acc[mt][nt][2] + b0;
            float v11 = acc[mt][nt][3] + b1;
            if (MODE == 1) { v00 *= scale; v01 *= scale; v10 *= scale; v11 *= scale; }
            if (MODE == 2) {
                v00 = 0.5f*v00*(1.0f + erff(v00*0.70710678118654752f));
                v01 = 0.5f*v01*(1.0f + erff(v01*0.70710678118654752f));
                v10 = 0.5f*v10*(1.0f + erff(v10*0.70710678118654752f));
                v11 = 0.5f*v11*(1.0f + erff(v11*0.70710678118654752f));
            }
            if (MODE == 3) {
                float2 r0 = *(const float2*)&res[(size_t)row0*N + col];
                float2 r1 = *(const float2*)&res[(size_t)row1*N + col];
                v00 += r0.x; v01 += r0.y; v10 += r1.x; v11 += r1.y;
            }
            *(float2*)&C[(size_t)row0*N + col] = make_float2(v00, v01);
            *(float2*)&C[(size_t)row1*N + col] = make_float2(v10, v11);
        }
    }
}

// ---------------------------------------------------------------------------
// Neighborhood attention, tiled: one block = 8 queries (same batch, same row i,
// consecutive j), 512 threads. KV patch (7 x 14 tokens, all heads) staged in
// dynamic SMEM once and reused by all 8 queries x 4 heads.
// ---------------------------------------------------------------------------
#define PATCH_TOK 98            // 7 * 14
#define KPAD 36
#define AT_THREADS 512

__global__ __launch_bounds__(AT_THREADS)
void nat_attn_kernel(const float* __restrict__ q,
                     const float* __restrict__ kv,
                     const float* __restrict__ rpb,
                     float* __restrict__ out)
{
    extern __shared__ float sm[];
    float* Ks = sm;                                   // [4][98][36]
    float* Vs = Ks + 4*PATCH_TOK*KPAD;                // [4][98][36]
    float* qs = Vs + 4*PATCH_TOK*KPAD;                // [8][128]
    float* ps = qs + 8*128;                           // [32][52]
    float* rs = ps + 32*52;                           // [676]

    const int blk = blockIdx.x;
    const int b   = blk >> 9;
    const int rem = blk & 511;
    const int i   = rem >> 3;
    const int jt  = (rem & 7) << 3;

    int i0  = i - 3;  if (i0 < 0) i0 = 0;  if (i0 > Hh - Kk) i0 = Hh - Kk;
    int jp0 = jt - 3; if (jp0 < 0) jp0 = 0; if (jp0 > Ww - 14) jp0 = Ww - 14;

    const int tid  = threadIdx.x;
    const int base = b * (Hh*Ww);

    for (int f = tid; f < PATCH_TOK*64; f += AT_THREADS) {
        int tok = f >> 6;
        int c4  = f & 63;
        int r   = tok / 14;
        int cc  = tok - r*14;
        int g   = base + (i0 + r)*Ww + (jp0 + cc);
        float4 v = *(const float4*)&kv[(size_t)g*(2*Cc) + c4*4];
        int c = c4*4;
        if (c < Cc) {
            int h = c >> 5, d = c & 31;
            *(float4*)&Ks[(h*PATCH_TOK + tok)*KPAD + d] = v;
        } else {
            int c2 = c - Cc;
            int h = c2 >> 5, d = c2 & 31;
            *(float4*)&Vs[(h*PATCH_TOK + tok)*KPAD + d] = v;
        }
    }
    for (int f = tid; f < 8*32; f += AT_THREADS) {
        int qq = f >> 5, c4 = f & 31;
        int g = base + i*Ww + (jt + qq);
        *(float4*)&qs[qq*Cc + c4*4] = *(const float4*)&q[(size_t)g*Cc + c4*4];
    }
    for (int f = tid; f < 676; f += AT_THREADS) rs[f] = rpb[f];
    __syncthreads();

    const int w    = tid >> 5;
    const int lane = tid & 31;

    #pragma unroll
    for (int s = 0; s < 2; s++) {
        const int task = w*2 + s;
        const int qq = task >> 2;
        const int h  = task & 3;
        const int j  = jt + qq;
        int j0 = j - 3; if (j0 < 0) j0 = 0; if (j0 > Ww - Kk) j0 = Ww - Kk;
        const int joff = j0 - jp0;

        float4 qv[8];
        #pragma unroll
        for (int u = 0; u < 8; u++)
            qv[u] = *(const float4*)&qs[qq*Cc + h*32 + u*4];

        float sc[2];
        #pragma unroll
        for (int r = 0; r < 2; r++) {
            int n = r*32 + lane;
            float val = -INFINITY;
            if (n < 49) {
                int ni = n / 7;
                int nj = n - ni*7;
                int lt = ni*14 + joff + nj;
                const float* kp = &Ks[(h*PATCH_TOK + lt)*KPAD];
                float a0 = 0.f, a1 = 0.f, a2 = 0.f, a3 = 0.f;
                #pragma unroll
                for (int u = 0; u < 8; u++) {
                    float4 kk4 = *(const float4*)&kp[u*4];
                    a0 = fmaf(qv[u].x, kk4.x, a0);
                    a1 = fmaf(qv[u].y, kk4.y, a1);
                    a2 = fmaf(qv[u].z, kk4.z, a2);
                    a3 = fmaf(qv[u].w, kk4.w, a3);
                }
                int ri = i0 + ni - i + (Kk - 1);
                int rj = j0 + nj - j + (Kk - 1);
                val = ((a0 + a1) + (a2 + a3)) + rs[h*169 + ri*13 + rj];
            }
            sc[r] = val;
        }

        float mx = fmaxf(sc[0], sc[1]);
        #pragma unroll
        for (int off = 16; off; off >>= 1)
            mx = fmaxf(mx, __shfl_xor_sync(0xffffffff, mx, off));
        float e0 = __expf(sc[0] - mx);
        float e1 = __expf(sc[1] - mx);
        float sum = e0 + e1;
        #pragma unroll
        for (int off = 16; off; off >>= 1)
            sum += __shfl_xor_sync(0xffffffff, sum, off);
        float rinv = 1.0f / sum;
        ps[task*52 + lane] = e0 * rinv;
        if (lane < 17) ps[task*52 + 32 + lane] = e1 * rinv;
        __syncwarp();

        float o = 0.0f;
        #pragma unroll
        for (int n = 0; n < 49; n++) {
            int ni = n / 7;
            int nj = n - ni*7;
            int lt = ni*14 + joff + nj;
            o = fmaf(ps[task*52 + n], Vs[(h*PATCH_TOK + lt)*KPAD + lane], o);
        }
        int g = base + i*Ww + j;
        out[(size_t)g*Cc + h*32 + lane] = o;
        __syncwarp();
    }
}

// ---------------------------------------------------------------------------
// Launch
// ---------------------------------------------------------------------------
extern "C" void kernel_launch(void* const* d_in, const int* in_sizes, int n_in,
                              void* d_out, int out_size)
{
    const float* query     = (const float*)d_in[0];
    const float* key_value = (const float*)d_in[1];
    const float* g1  = (const float*)d_in[2];
    const float* b1  = (const float*)d_in[3];
    const float* g2  = (const float*)d_in[4];
    const float* b2  = (const float*)d_in[5];
    const float* g3  = (const float*)d_in[6];
    const float* b3  = (const float*)d_in[7];
    const float* Wq  = (const float*)d_in[8];
    const float* bq  = (const float*)d_in[9];
    const float* Wkv = (const float*)d_in[10];
    const float* bkv = (const float*)d_in[11];
    const float* Wp  = (const float*)d_in[12];
    const float* bp  = (const float*)d_in[13];
    const float* rpb = (const float*)d_in[14];
    const float* W1  = (const float*)d_in[15];
    const float* bm1 = (const float*)d_in[16];
    const float* W2  = (const float*)d_in[17];
    const float* bm2 = (const float*)d_in[18];
    float* out = (float*)d_out;

    float* qn     = nullptr; cudaGetSymbolAddress((void**)&qn,     g_qn);
    float* kvn    = nullptr; cudaGetSymbolAddress((void**)&kvn,    g_kvn);
    float* qbuf   = nullptr; cudaGetSymbolAddress((void**)&qbuf,   g_q);
    float* kvbuf  = nullptr; cudaGetSymbolAddress((void**)&kvbuf,  g_kv);
    float* attn   = nullptr; cudaGetSymbolAddress((void**)&attn,   g_attn);
    float* xbuf   = nullptr; cudaGetSymbolAddress((void**)&xbuf,   g_x);
    float* hln    = nullptr; cudaGetSymbolAddress((void**)&hln,    g_hln);
    float* hidden = nullptr; cudaGetSymbolAddress((void**)&hidden, g_hidden);

    static bool attr_set = false;
    const int at_smem = (2*4*PATCH_TOK*KPAD + 8*128 + 32*52 + 676) * (int)sizeof(float);
    if (!attr_set) {
        cudaFuncSetAttribute(nat_attn_kernel,
                             cudaFuncAttributeMaxDynamicSharedMemorySize, at_smem);
        attr_set = true;
    }

    const int lnBlocks = (NTOK * 32) / 256;

    // 1) LayerNorms
    ln_kernel<<<lnBlocks, 256>>>(query,     g1, b1, qn,  NTOK);
    ln_kernel<<<lnBlocks, 256>>>(key_value, g2, b2, kvn, NTOK);

    // 2) Q projection (scaled) and KV projection — tf32 tensor cores
    gemm_tc<1><<<dim3(Cc/128,   NTOK/128), 256>>>(qn,  Wq,  bq,  nullptr, qbuf,  NTOK, Cc,   Cc, 0.17677669529663689f);
    gemm_tc<0><<<dim3(2*Cc/128, NTOK/128), 256>>>(kvn, Wkv, bkv, nullptr, kvbuf, NTOK, 2*Cc, Cc, 1.0f);

    // 3) Neighborhood attention (tiled)
    nat_attn_kernel<<<Bq*Hh*(Ww/8), AT_THREADS, at_smem>>>(qbuf, kvbuf, rpb, attn);

    // 4) Output projection + residual (shortcut = key_value)
    gemm_tc<3><<<dim3(Cc/128, NTOK/128), 256>>>(attn, Wp, bp, key_value, xbuf, NTOK, Cc, Cc, 1.0f);

    // 5) LN3 + MLP
    ln_kernel<<<lnBlocks, 256>>>(xbuf, g3, b3, hln, NTOK);
    gemm_tc<2><<<dim3(MLPD/128, NTOK/128), 256>>>(hln,    W1, bm1, nullptr, hidden, NTOK, MLPD, Cc,   1.0f);
    gemm_tc<3><<<dim3(Cc/128,   NTOK/128), 256>>>(hidden, W2, bm2, xbuf,    out,    NTOK, Cc,   MLPD, 1.0f);
}

// round 6
// speedup vs baseline: 1.2491x; 1.2491x over previous
#include <cuda_runtime.h>
#include <cuda_bf16.h>
#include <math.h>

// Problem constants
#define Bq  4
#define Hh  64
#define Ww  64
#define Cc  128
#define NHh 4
#define Kk  7
#define HDd 32
#define MLPD 512
#define NTOK (Bq*Hh*Ww)   // 16384

typedef __nv_bfloat16  bf16;
typedef __nv_bfloat162 bf162;

// Scratch (device globals — no allocation allowed in kernel_launch)
__device__ __align__(16) bf16  g_qn    [NTOK*Cc];
__device__ __align__(16) bf16  g_kvn   [NTOK*Cc];
__device__ __align__(16) float g_q     [NTOK*Cc];
__device__ __align__(16) bf16  g_kv    [NTOK*2*Cc];
__device__ __align__(16) bf16  g_attn  [NTOK*Cc];
__device__ __align__(16) float g_x     [NTOK*Cc];
__device__ __align__(16) bf16  g_hln   [NTOK*Cc];
__device__ __align__(16) bf16  g_hidden[NTOK*MLPD];

__device__ __forceinline__ unsigned s2u(const void* p) {
    return (unsigned)__cvta_generic_to_shared(p);
}

// ---------------------------------------------------------------------------
// LayerNorm: one warp per token, bf16 output
// ---------------------------------------------------------------------------
__global__ void ln_kernel_bf16(const float* __restrict__ in,
                               const float* __restrict__ g,
                               const float* __restrict__ b,
                               bf16* __restrict__ out, int ntok)
{
    int warp = (blockIdx.x * blockDim.x + threadIdx.x) >> 5;
    int lane = threadIdx.x & 31;
    if (warp >= ntok) return;

    const float4 v = *(const float4*)&in[(size_t)warp*Cc + lane*4];
    float s  = v.x + v.y + v.z + v.w;
    float sq = v.x*v.x + v.y*v.y + v.z*v.z + v.w*v.w;
    #pragma unroll
    for (int off = 16; off; off >>= 1) {
        s  += __shfl_xor_sync(0xffffffff, s,  off);
        sq += __shfl_xor_sync(0xffffffff, sq, off);
    }
    float mean = s * (1.0f/Cc);
    float var  = sq * (1.0f/Cc) - mean*mean;
    float inv  = rsqrtf(var + 1e-5f);

    const float4 gv = *(const float4*)&g[lane*4];
    const float4 bv = *(const float4*)&b[lane*4];
    bf162 o0 = __float22bfloat162_rn(make_float2((v.x-mean)*inv*gv.x + bv.x,
                                                 (v.y-mean)*inv*gv.y + bv.y));
    bf162 o1 = __float22bfloat162_rn(make_float2((v.z-mean)*inv*gv.z + bv.z,
                                                 (v.w-mean)*inv*gv.w + bv.w));
    uint2 pk; pk.x = *(unsigned*)&o0; pk.y = *(unsigned*)&o1;
    *(uint2*)&out[(size_t)warp*Cc + lane*4] = pk;
}

// ---------------------------------------------------------------------------
// bf16 tensor-core GEMM: C = epilogue(A[MxK](bf16) @ W[KxN](fp32) + bias)
//   MODE 0: +bias | 1: (+bias)*scale | 2: gelu(+bias) | 3: +bias+res
//   OUTBF: 1 -> write bf16, 0 -> write fp32
// CTA 64x128, BK=32 double buffered, 128 threads (2m x 2n warps, warp 32x64),
// mma.sync m16n8k16 bf16, fragments via ldmatrix.
// A smem [m][k] pitch 40 bf16 (80B); B smem [k][n] pitch 136 bf16 (272B).
// Requires M%64==0, N%128==0, K%32==0.
// ---------------------------------------------------------------------------
#define APITCH 40
#define BPITCH 136

template <int MODE, int OUTBF>
__global__ __launch_bounds__(128)
void gemm_bf(const bf16* __restrict__ A,
             const float* __restrict__ W,
             const float* __restrict__ bias,
             const float* __restrict__ res,
             void* __restrict__ Cout,
             int M, int N, int K, float scale)
{
    __shared__ bf16 As[2][64*APITCH];
    __shared__ bf16 Bs[2][32*BPITCH];

    const int tid  = threadIdx.x;
    const int bm   = blockIdx.y * 64;
    const int bn   = blockIdx.x * 128;
    const int warp = tid >> 5;
    const int lane = tid & 31;
    const int g    = lane >> 2;
    const int t    = lane & 3;
    const int warpM = warp >> 1;       // 0..1
    const int warpN = warp & 1;        // 0..1

    // global staging maps
    const int arow = tid >> 2;              // not used directly; see chunk map
    (void)arow;
    // A: 256 chunks of 8 bf16; thread handles chunk tid and tid+128
    const int ch0_r = tid >> 2,      ch0_c = tid & 3;
    const int ch1_r = (tid+128) >> 2, ch1_c = (tid+128) & 3;
    // B: thread row/colbase
    const int brow = tid >> 2;
    const int bcol = (tid & 3) * 32;

    const uint4* A4r0 = (const uint4*)(A + (size_t)(bm + ch0_r) * K);
    const uint4* A4r1 = (const uint4*)(A + (size_t)(bm + ch1_r) * K);
    const float* Wg   = W + (size_t)brow * N + bn + bcol;

    float acc[2][8][4];
    #pragma unroll
    for (int mt = 0; mt < 2; mt++)
        #pragma unroll
        for (int nt = 0; nt < 8; nt++)
            #pragma unroll
            for (int e = 0; e < 4; e++) acc[mt][nt][e] = 0.0f;

    const int ntile = K / 32;

    // lane-dependent ldmatrix address components
    const unsigned aBase0 = s2u(As[0]);
    const unsigned bBase0 = s2u(Bs[0]);
    const unsigned aBufSz = 64*APITCH*2;
    const unsigned bBufSz = 32*BPITCH*2;
    const int a_row_sel = lane & 15;
    const int a_k_sel   = (lane >> 4) << 3;
    const int b_k_sel   = (lane & 7) + (((lane >> 3) & 1) << 3);
    const int b_n_sel   = (lane >> 4) << 3;

    uint4  av0, av1;
    float4 wv[8];

    // prologue: tile 0
    av0 = A4r0[0*4 + ch0_c];
    av1 = A4r1[0*4 + ch1_c];
    #pragma unroll
    for (int u = 0; u < 8; u++) wv[u] = *(const float4*)(Wg + u*4);
    {
        *(uint4*)&As[0][ch0_r*APITCH + ch0_c*8] = av0;
        *(uint4*)&As[0][ch1_r*APITCH + ch1_c*8] = av1;
        #pragma unroll
        for (int u = 0; u < 8; u++) {
            bf162 lo = __float22bfloat162_rn(make_float2(wv[u].x, wv[u].y));
            bf162 hi = __float22bfloat162_rn(make_float2(wv[u].z, wv[u].w));
            uint2 pk; pk.x = *(unsigned*)&lo; pk.y = *(unsigned*)&hi;
            *(uint2*)&Bs[0][brow*BPITCH + bcol + u*4] = pk;
        }
    }
    __syncthreads();

    for (int kt = 0; kt < ntile; kt++) {
        const int cur = kt & 1;
        if (kt + 1 < ntile) {
            av0 = A4r0[(kt+1)*4 + ch0_c];
            av1 = A4r1[(kt+1)*4 + ch1_c];
            const float* Wp = Wg + (size_t)(kt+1) * 32 * N;
            #pragma unroll
            for (int u = 0; u < 8; u++) wv[u] = *(const float4*)(Wp + u*4);
        }

        const unsigned aB = aBase0 + cur*aBufSz;
        const unsigned bB = bBase0 + cur*bBufSz;
        #pragma unroll
        for (int kk = 0; kk < 32; kk += 16) {
            unsigned af[2][4], bf[8][2];
            #pragma unroll
            for (int mt = 0; mt < 2; mt++) {
                unsigned addr = aB + ((warpM*32 + mt*16 + a_row_sel)*APITCH + kk + a_k_sel)*2;
                asm volatile("ldmatrix.sync.aligned.m8n8.x4.shared.b16 {%0,%1,%2,%3}, [%4];"
                    : "=r"(af[mt][0]), "=r"(af[mt][1]), "=r"(af[mt][2]), "=r"(af[mt][3])
                    : "r"(addr));
            }
            #pragma unroll
            for (int np = 0; np < 4; np++) {
                unsigned r0, r1, r2, r3;
                unsigned addr = bB + ((kk + b_k_sel)*BPITCH + warpN*64 + np*16 + b_n_sel)*2;
                asm volatile("ldmatrix.sync.aligned.m8n8.x4.trans.shared.b16 {%0,%1,%2,%3}, [%4];"
                    : "=r"(r0), "=r"(r1), "=r"(r2), "=r"(r3)
                    : "r"(addr));
                bf[2*np  ][0] = r0; bf[2*np  ][1] = r1;
                bf[2*np+1][0] = r2; bf[2*np+1][1] = r3;
            }
            #pragma unroll
            for (int mt = 0; mt < 2; mt++)
                #pragma unroll
                for (int nt = 0; nt < 8; nt++)
                    asm volatile(
                        "mma.sync.aligned.m16n8k16.row.col.f32.bf16.bf16.f32 "
                        "{%0,%1,%2,%3}, {%4,%5,%6,%7}, {%8,%9}, {%0,%1,%2,%3};"
                        : "+f"(acc[mt][nt][0]), "+f"(acc[mt][nt][1]),
                          "+f"(acc[mt][nt][2]), "+f"(acc[mt][nt][3])
                        : "r"(af[mt][0]), "r"(af[mt][1]), "r"(af[mt][2]), "r"(af[mt][3]),
                          "r"(bf[nt][0]), "r"(bf[nt][1]));
        }

        if (kt + 1 < ntile) {
            const int nxt = cur ^ 1;
            *(uint4*)&As[nxt][ch0_r*APITCH + ch0_c*8] = av0;
            *(uint4*)&As[nxt][ch1_r*APITCH + ch1_c*8] = av1;
            #pragma unroll
            for (int u = 0; u < 8; u++) {
                bf162 lo = __float22bfloat162_rn(make_float2(wv[u].x, wv[u].y));
                bf162 hi = __float22bfloat162_rn(make_float2(wv[u].z, wv[u].w));
                uint2 pk; pk.x = *(unsigned*)&lo; pk.y = *(unsigned*)&hi;
                *(uint2*)&Bs[nxt][brow*BPITCH + bcol + u*4] = pk;
            }
        }
        __syncthreads();
    }

    // epilogue
    float* Cf  = (float*)Cout;
    bf16*  Cb  = (bf16*)Cout;
    #pragma unroll
    for (int mt = 0; mt < 2; mt++) {
        int row0 = bm + warpM*32 + mt*16 + g;
        int row1 = row0 + 8;
        #pragma unroll
        for (int nt = 0; nt < 8; nt++) {
            int col = bn + warpN*64 + nt*8 + 2*t;
            float b0 = bias[col], b1 = bias[col+1];
            float v00 = acc[mt][nt][0] + b0;
            float v01 = acc[mt][nt][1] + b1;
            float v10 = acc[mt][nt][2] + b0;
            float v11 = acc[mt][nt][3] + b1;
            if (MODE == 1) { v00 *= scale; v01 *= scale; v10 *= scale; v11 *= scale; }
            if (MODE == 2) {
                v00 = 0.5f*v00*(1.0f + erff(v00*0.70710678118654752f));
                v01 = 0.5f*v01*(1.0f + erff(v01*0.70710678118654752f));
                v10 = 0.5f*v10*(1.0f + erff(v10*0.70710678118654752f));
                v11 = 0.5f*v11*(1.0f + erff(v11*0.70710678118654752f));
            }
            if (MODE == 3) {
                float2 r0 = *(const float2*)&res[(size_t)row0*N + col];
                float2 r1 = *(const float2*)&res[(size_t)row1*N + col];
                v00 += r0.x; v01 += r0.y; v10 += r1.x; v11 += r1.y;
            }
            if (OUTBF) {
                bf162 p0 = __float22bfloat162_rn(make_float2(v00, v01));
                bf162 p1 = __float22bfloat162_rn(make_float2(v10, v11));
                *(unsigned*)&Cb[(size_t)row0*N + col] = *(unsigned*)&p0;
                *(unsigned*)&Cb[(size_t)row1*N + col] = *(unsigned*)&p1;
            } else {
                *(float2*)&Cf[(size_t)row0*N + col] = make_float2(v00, v01);
                *(float2*)&Cf[(size_t)row1*N + col] = make_float2(v10, v11);
            }
        }
    }
}

// ---------------------------------------------------------------------------
// Neighborhood attention v2: block = 8x4 query tile, 512 threads (16 warps).
// KV patch 14x10 = 140 tokens staged as bf16. q fp32. Softmax weights kept in
// registers, broadcast via shfl for the V pass. Output bf16.
// ---------------------------------------------------------------------------
#define PR 14
#define PC 10
#define PTOK 140
#define DPAD 40
#define AT_THREADS 512

__global__ __launch_bounds__(AT_THREADS)
void nat_attn2(const float* __restrict__ q,
               const bf16* __restrict__ kv,
               const float* __restrict__ rpb,
               bf16* __restrict__ out)
{
    extern __shared__ char smraw[];
    bf16*  Ks = (bf16*)smraw;                  // [4][140][40]
    bf16*  Vs = Ks + 4*PTOK*DPAD;              // [4][140][40]
    float* qs = (float*)(Vs + 4*PTOK*DPAD);    // [32][128]
    float* rs = qs + 32*128;                   // [676]

    const int blk = blockIdx.x;                // 512 = 4 * 8 * 16
    const int b   = blk >> 7;
    const int rem = blk & 127;
    const int it  = (rem >> 4) << 3;
    const int jt  = (rem & 15) << 2;

    int ip0 = it - 3; if (ip0 < 0) ip0 = 0; if (ip0 > Hh - PR) ip0 = Hh - PR;
    int jp0 = jt - 3; if (jp0 < 0) jp0 = 0; if (jp0 > Ww - PC) jp0 = Ww - PC;

    const int tid  = threadIdx.x;
    const int base = b * (Hh*Ww);

    // stage KV (140 tokens x 256 bf16 = 140*32 uint4)
    const uint4* kv4 = (const uint4*)kv;
    for (int f = tid; f < PTOK*32; f += AT_THREADS) {
        int tok = f >> 5;
        int c8  = f & 31;
        int r   = tok / PC;
        int cc  = tok - r*PC;
        int g   = base + (ip0 + r)*Ww + (jp0 + cc);
        uint4 v = kv4[(size_t)g*32 + c8];
        int c = c8 * 8;
        if (c < Cc) {
            *(uint4*)&Ks[((c>>5)*PTOK + tok)*DPAD + (c & 31)] = v;
        } else {
            int c2 = c - Cc;
            *(uint4*)&Vs[((c2>>5)*PTOK + tok)*DPAD + (c2 & 31)] = v;
        }
    }
    // stage q fp32 (32 queries x 128)
    for (int f = tid; f < 32*32; f += AT_THREADS) {
        int qq = f >> 5, c4 = f & 31;
        int qi = qq >> 2, qj = qq & 3;
        int g = base + (it + qi)*Ww + (jt + qj);
        *(float4*)&qs[qq*Cc + c4*4] = *(const float4*)&q[(size_t)g*Cc + c4*4];
    }
    for (int f = tid; f < 676; f += AT_THREADS) rs[f] = rpb[f];
    __syncthreads();

    const int w    = tid >> 5;
    const int lane = tid & 31;

    #pragma unroll
    for (int s = 0; s < 8; s++) {
        const int task = w*8 + s;            // 0..127
        const int qq = task >> 2;
        const int h  = task & 3;
        const int qi = qq >> 2, qj = qq & 3;
        const int gi = it + qi, gj = jt + qj;
        int i0 = gi - 3; if (i0 < 0) i0 = 0; if (i0 > Hh - Kk) i0 = Hh - Kk;
        int j0 = gj - 3; if (j0 < 0) j0 = 0; if (j0 > Ww - Kk) j0 = Ww - Kk;
        const int ioff = i0 - ip0;
        const int joff = j0 - jp0;

        // q slice (broadcast loads)
        float qf[32];
        #pragma unroll
        for (int u = 0; u < 8; u++) {
            float4 t4 = *(const float4*)&qs[qq*Cc + h*32 + u*4];
            qf[u*4+0] = t4.x; qf[u*4+1] = t4.y; qf[u*4+2] = t4.z; qf[u*4+3] = t4.w;
        }

        // scores: lane handles neighbors lane and lane+32
        float sc[2];
        #pragma unroll
        for (int r = 0; r < 2; r++) {
            int n = r*32 + lane;
            float val = -INFINITY;
            if (n < 49) {
                int ni = n / 7;
                int nj = n - ni*7;
                int lt = (ioff + ni)*PC + joff + nj;
                const uint4* kp = (const uint4*)&Ks[(h*PTOK + lt)*DPAD];
                float a0 = 0.f;
                #pragma unroll
                for (int u = 0; u < 4; u++) {
                    uint4 kk4 = kp[u];
                    float2 f0 = __bfloat1622float2(*(const bf162*)&kk4.x);
                    float2 f1 = __bfloat1622float2(*(const bf162*)&kk4.y);
                    float2 f2 = __bfloat1622float2(*(const bf162*)&kk4.z);
                    float2 f3 = __bfloat1622float2(*(const bf162*)&kk4.w);
                    a0 = fmaf(qf[u*8+0], f0.x, a0);
                    a0 = fmaf(qf[u*8+1], f0.y, a0);
                    a0 = fmaf(qf[u*8+2], f1.x, a0);
                    a0 = fmaf(qf[u*8+3], f1.y, a0);
                    a0 = fmaf(qf[u*8+4], f2.x, a0);
                    a0 = fmaf(qf[u*8+5], f2.y, a0);
                    a0 = fmaf(qf[u*8+6], f3.x, a0);
                    a0 = fmaf(qf[u*8+7], f3.y, a0);
                }
                int ri = i0 + ni - gi + (Kk - 1);
                int rj = j0 + nj - gj + (Kk - 1);
                val = a0 + rs[h*169 + ri*13 + rj];
            }
            sc[r] = val;
        }

        // softmax over 49 within warp
        float mx = fmaxf(sc[0], sc[1]);
        #pragma unroll
        for (int off = 16; off; off >>= 1)
            mx = fmaxf(mx, __shfl_xor_sync(0xffffffff, mx, off));
        float e0 = __expf(sc[0] - mx);
        float e1 = __expf(sc[1] - mx);
        float sum = e0 + e1;
        #pragma unroll
        for (int off = 16; off; off >>= 1)
            sum += __shfl_xor_sync(0xffffffff, sum, off);
        float rinv = 1.0f / sum;
        float p0 = e0 * rinv;
        float p1 = e1 * rinv;

        // V pass: lane = dim, p broadcast via shfl
        float o = 0.0f;
        #pragma unroll
        for (int n = 0; n < 49; n++) {
            float pn = (n < 32) ? __shfl_sync(0xffffffff, p0, n)
                                : __shfl_sync(0xffffffff, p1, n - 32);
            int ni = n / 7;
            int nj = n - ni*7;
            int lt = (ioff + ni)*PC + joff + nj;
            float vv = __bfloat162float(Vs[(h*PTOK + lt)*DPAD + lane]);
            o = fmaf(pn, vv, o);
        }
        int g = base + gi*Ww + gj;
        out[(size_t)g*Cc + h*32 + lane] = __float2bfloat16(o);
    }
}

// ---------------------------------------------------------------------------
// Launch
// ---------------------------------------------------------------------------
extern "C" void kernel_launch(void* const* d_in, const int* in_sizes, int n_in,
                              void* d_out, int out_size)
{
    const float* query     = (const float*)d_in[0];
    const float* key_value = (const float*)d_in[1];
    const float* g1  = (const float*)d_in[2];
    const float* b1  = (const float*)d_in[3];
    const float* g2  = (const float*)d_in[4];
    const float* b2  = (const float*)d_in[5];
    const float* g3  = (const float*)d_in[6];
    const float* b3  = (const float*)d_in[7];
    const float* Wq  = (const float*)d_in[8];
    const float* bq  = (const float*)d_in[9];
    const float* Wkv = (const float*)d_in[10];
    const float* bkv = (const float*)d_in[11];
    const float* Wp  = (const float*)d_in[12];
    const float* bp  = (const float*)d_in[13];
    const float* rpb = (const float*)d_in[14];
    const float* W1  = (const float*)d_in[15];
    const float* bm1 = (const float*)d_in[16];
    const float* W2  = (const float*)d_in[17];
    const float* bm2 = (const float*)d_in[18];
    float* out = (float*)d_out;

    bf16*  qn     = nullptr; cudaGetSymbolAddress((void**)&qn,     g_qn);
    bf16*  kvn    = nullptr; cudaGetSymbolAddress((void**)&kvn,    g_kvn);
    float* qbuf   = nullptr; cudaGetSymbolAddress((void**)&qbuf,   g_q);
    bf16*  kvbuf  = nullptr; cudaGetSymbolAddress((void**)&kvbuf,  g_kv);
    bf16*  attn   = nullptr; cudaGetSymbolAddress((void**)&attn,   g_attn);
    float* xbuf   = nullptr; cudaGetSymbolAddress((void**)&xbuf,   g_x);
    bf16*  hln    = nullptr; cudaGetSymbolAddress((void**)&hln,    g_hln);
    bf16*  hidden = nullptr; cudaGetSymbolAddress((void**)&hidden, g_hidden);

    static bool attr_set = false;
    const int at_smem = (2*4*PTOK*DPAD)*2 + (32*128 + 676)*4;   // 108688 B
    if (!attr_set) {
        cudaFuncSetAttribute(nat_attn2,
                             cudaFuncAttributeMaxDynamicSharedMemorySize, at_smem);
        attr_set = true;
    }

    const int lnBlocks = (NTOK * 32) / 256;

    // 1) LayerNorms -> bf16
    ln_kernel_bf16<<<lnBlocks, 256>>>(query,     g1, b1, qn,  NTOK);
    ln_kernel_bf16<<<lnBlocks, 256>>>(key_value, g2, b2, kvn, NTOK);

    // 2) Q projection (scaled, fp32 out) and KV projection (bf16 out)
    gemm_bf<1,0><<<dim3(Cc/128,   NTOK/64), 128>>>(qn,  Wq,  bq,  nullptr, qbuf,  NTOK, Cc,   Cc, 0.17677669529663689f);
    gemm_bf<0,1><<<dim3(2*Cc/128, NTOK/64), 128>>>(kvn, Wkv, bkv, nullptr, kvbuf, NTOK, 2*Cc, Cc, 1.0f);

    // 3) Neighborhood attention (bf16 KV, bf16 out)
    nat_attn2<<<Bq*(Hh/8)*(Ww/4), AT_THREADS, at_smem>>>(qbuf, kvbuf, rpb, attn);

    // 4) Output projection + residual (fp32 out)
    gemm_bf<3,0><<<dim3(Cc/128, NTOK/64), 128>>>(attn, Wp, bp, key_value, xbuf, NTOK, Cc, Cc, 1.0f);

    // 5) LN3 + MLP
    ln_kernel_bf16<<<lnBlocks, 256>>>(xbuf, g3, b3, hln, NTOK);
    gemm_bf<2,1><<<dim3(MLPD/128, NTOK/64), 128>>>(hln,    W1, bm1, nullptr, hidden, NTOK, MLPD, Cc,   1.0f);
    gemm_bf<3,0><<<dim3(Cc/128,   NTOK/64), 128>>>(hidden, W2, bm2, xbuf,    out,    NTOK, Cc,   MLPD, 1.0f);
}

// round 7
// speedup vs baseline: 1.2602x; 1.0089x over previous
#include <cuda_runtime.h>
#include <cuda_bf16.h>
#include <math.h>

// Problem constants
#define Bq  4
#define Hh  64
#define Ww  64
#define Cc  128
#define NHh 4
#define Kk  7
#define HDd 32
#define MLPD 512
#define NTOK (Bq*Hh*Ww)   // 16384

typedef __nv_bfloat16  bf16;
typedef __nv_bfloat162 bf162;

// Scratch (device globals — no allocation allowed in kernel_launch)
__device__ __align__(16) bf16  g_qn    [NTOK*Cc];
__device__ __align__(16) bf16  g_kvn   [NTOK*Cc];
__device__ __align__(16) float g_q     [NTOK*Cc];
__device__ __align__(16) bf16  g_kv    [NTOK*2*Cc];
__device__ __align__(16) bf16  g_attn  [NTOK*Cc];
__device__ __align__(16) float g_x     [NTOK*Cc];
__device__ __align__(16) bf16  g_hln   [NTOK*Cc];
__device__ __align__(16) bf16  g_hidden[NTOK*MLPD];

__device__ __forceinline__ unsigned s2u(const void* p) {
    return (unsigned)__cvta_generic_to_shared(p);
}

// ---------------------------------------------------------------------------
// LayerNorm: one warp per token, bf16 output
// ---------------------------------------------------------------------------
__global__ void ln_kernel_bf16(const float* __restrict__ in,
                               const float* __restrict__ g,
                               const float* __restrict__ b,
                               bf16* __restrict__ out, int ntok)
{
    int warp = (blockIdx.x * blockDim.x + threadIdx.x) >> 5;
    int lane = threadIdx.x & 31;
    if (warp >= ntok) return;

    const float4 v = *(const float4*)&in[(size_t)warp*Cc + lane*4];
    float s  = v.x + v.y + v.z + v.w;
    float sq = v.x*v.x + v.y*v.y + v.z*v.z + v.w*v.w;
    #pragma unroll
    for (int off = 16; off; off >>= 1) {
        s  += __shfl_xor_sync(0xffffffff, s,  off);
        sq += __shfl_xor_sync(0xffffffff, sq, off);
    }
    float mean = s * (1.0f/Cc);
    float var  = sq * (1.0f/Cc) - mean*mean;
    float inv  = rsqrtf(var + 1e-5f);

    const float4 gv = *(const float4*)&g[lane*4];
    const float4 bv = *(const float4*)&b[lane*4];
    bf162 o0 = __float22bfloat162_rn(make_float2((v.x-mean)*inv*gv.x + bv.x,
                                                 (v.y-mean)*inv*gv.y + bv.y));
    bf162 o1 = __float22bfloat162_rn(make_float2((v.z-mean)*inv*gv.z + bv.z,
                                                 (v.w-mean)*inv*gv.w + bv.w));
    uint2 pk; pk.x = *(unsigned*)&o0; pk.y = *(unsigned*)&o1;
    *(uint2*)&out[(size_t)warp*Cc + lane*4] = pk;
}

// ---------------------------------------------------------------------------
// bf16 tensor-core GEMM: C = epilogue(A[MxK](bf16) @ W[KxN](fp32) + bias)
//   MODE 0: +bias | 1: (+bias)*scale | 2: gelu(+bias) | 3: +bias+res
//   OUTBF: 1 -> write bf16, 0 -> write fp32
// CTA 64x128, BK=32 double buffered, 128 threads (2m x 2n warps, warp 32x64),
// mma.sync m16n8k16 bf16, fragments via ldmatrix.
// A smem [m][k] pitch 40 bf16 (80B); B smem [k][n] pitch 136 bf16 (272B).
// Requires M%64==0, N%128==0, K%32==0.
// ---------------------------------------------------------------------------
#define APITCH 40
#define BPITCH 136

template <int MODE, int OUTBF>
__global__ __launch_bounds__(128)
void gemm_bf(const bf16* __restrict__ A,
             const float* __restrict__ W,
             const float* __restrict__ bias,
             const float* __restrict__ res,
             void* __restrict__ Cout,
             int M, int N, int K, float scale)
{
    __shared__ bf16 As[2][64*APITCH];
    __shared__ bf16 Bs[2][32*BPITCH];

    const int tid  = threadIdx.x;
    const int bm   = blockIdx.y * 64;
    const int bn   = blockIdx.x * 128;
    const int warp = tid >> 5;
    const int lane = tid & 31;
    const int g    = lane >> 2;
    const int t    = lane & 3;
    const int warpM = warp >> 1;       // 0..1
    const int warpN = warp & 1;        // 0..1

    // global staging maps
    const int arow = tid >> 2;              // not used directly; see chunk map
    (void)arow;
    // A: 256 chunks of 8 bf16; thread handles chunk tid and tid+128
    const int ch0_r = tid >> 2,      ch0_c = tid & 3;
    const int ch1_r = (tid+128) >> 2, ch1_c = (tid+128) & 3;
    // B: thread row/colbase
    const int brow = tid >> 2;
    const int bcol = (tid & 3) * 32;

    const uint4* A4r0 = (const uint4*)(A + (size_t)(bm + ch0_r) * K);
    const uint4* A4r1 = (const uint4*)(A + (size_t)(bm + ch1_r) * K);
    const float* Wg   = W + (size_t)brow * N + bn + bcol;

    float acc[2][8][4];
    #pragma unroll
    for (int mt = 0; mt < 2; mt++)
        #pragma unroll
        for (int nt = 0; nt < 8; nt++)
            #pragma unroll
            for (int e = 0; e < 4; e++) acc[mt][nt][e] = 0.0f;

    const int ntile = K / 32;

    // lane-dependent ldmatrix address components
    const unsigned aBase0 = s2u(As[0]);
    const unsigned bBase0 = s2u(Bs[0]);
    const unsigned aBufSz = 64*APITCH*2;
    const unsigned bBufSz = 32*BPITCH*2;
    const int a_row_sel = lane & 15;
    const int a_k_sel   = (lane >> 4) << 3;
    const int b_k_sel   = (lane & 7) + (((lane >> 3) & 1) << 3);
    const int b_n_sel   = (lane >> 4) << 3;

    uint4  av0, av1;
    float4 wv[8];

    // prologue: tile 0
    av0 = A4r0[0*4 + ch0_c];
    av1 = A4r1[0*4 + ch1_c];
    #pragma unroll
    for (int u = 0; u < 8; u++) wv[u] = *(const float4*)(Wg + u*4);
    {
        *(uint4*)&As[0][ch0_r*APITCH + ch0_c*8] = av0;
        *(uint4*)&As[0][ch1_r*APITCH + ch1_c*8] = av1;
        #pragma unroll
        for (int u = 0; u < 8; u++) {
            bf162 lo = __float22bfloat162_rn(make_float2(wv[u].x, wv[u].y));
            bf162 hi = __float22bfloat162_rn(make_float2(wv[u].z, wv[u].w));
            uint2 pk; pk.x = *(unsigned*)&lo; pk.y = *(unsigned*)&hi;
            *(uint2*)&Bs[0][brow*BPITCH + bcol + u*4] = pk;
        }
    }
    __syncthreads();

    for (int kt = 0; kt < ntile; kt++) {
        const int cur = kt & 1;
        if (kt + 1 < ntile) {
            av0 = A4r0[(kt+1)*4 + ch0_c];
            av1 = A4r1[(kt+1)*4 + ch1_c];
            const float* Wp = Wg + (size_t)(kt+1) * 32 * N;
            #pragma unroll
            for (int u = 0; u < 8; u++) wv[u] = *(const float4*)(Wp + u*4);
        }

        const unsigned aB = aBase0 + cur*aBufSz;
        const unsigned bB = bBase0 + cur*bBufSz;
        #pragma unroll
        for (int kk = 0; kk < 32; kk += 16) {
            unsigned af[2][4], bf[8][2];
            #pragma unroll
            for (int mt = 0; mt < 2; mt++) {
                unsigned addr = aB + ((warpM*32 + mt*16 + a_row_sel)*APITCH + kk + a_k_sel)*2;
                asm volatile("ldmatrix.sync.aligned.m8n8.x4.shared.b16 {%0,%1,%2,%3}, [%4];"
                    : "=r"(af[mt][0]), "=r"(af[mt][1]), "=r"(af[mt][2]), "=r"(af[mt][3])
                    : "r"(addr));
            }
            #pragma unroll
            for (int np = 0; np < 4; np++) {
                unsigned r0, r1, r2, r3;
                unsigned addr = bB + ((kk + b_k_sel)*BPITCH + warpN*64 + np*16 + b_n_sel)*2;
                asm volatile("ldmatrix.sync.aligned.m8n8.x4.trans.shared.b16 {%0,%1,%2,%3}, [%4];"
                    : "=r"(r0), "=r"(r1), "=r"(r2), "=r"(r3)
                    : "r"(addr));
                bf[2*np  ][0] = r0; bf[2*np  ][1] = r1;
                bf[2*np+1][0] = r2; bf[2*np+1][1] = r3;
            }
            #pragma unroll
            for (int mt = 0; mt < 2; mt++)
                #pragma unroll
                for (int nt = 0; nt < 8; nt++)
                    asm volatile(
                        "mma.sync.aligned.m16n8k16.row.col.f32.bf16.bf16.f32 "
                        "{%0,%1,%2,%3}, {%4,%5,%6,%7}, {%8,%9}, {%0,%1,%2,%3};"
                        : "+f"(acc[mt][nt][0]), "+f"(acc[mt][nt][1]),
                          "+f"(acc[mt][nt][2]), "+f"(acc[mt][nt][3])
                        : "r"(af[mt][0]), "r"(af[mt][1]), "r"(af[mt][2]), "r"(af[mt][3]),
                          "r"(bf[nt][0]), "r"(bf[nt][1]));
        }

        if (kt + 1 < ntile) {
            const int nxt = cur ^ 1;
            *(uint4*)&As[nxt][ch0_r*APITCH + ch0_c*8] = av0;
            *(uint4*)&As[nxt][ch1_r*APITCH + ch1_c*8] = av1;
            #pragma unroll
            for (int u = 0; u < 8; u++) {
                bf162 lo = __float22bfloat162_rn(make_float2(wv[u].x, wv[u].y));
                bf162 hi = __float22bfloat162_rn(make_float2(wv[u].z, wv[u].w));
                uint2 pk; pk.x = *(unsigned*)&lo; pk.y = *(unsigned*)&hi;
                *(uint2*)&Bs[nxt][brow*BPITCH + bcol + u*4] = pk;
            }
        }
        __syncthreads();
    }

    // epilogue
    float* Cf  = (float*)Cout;
    bf16*  Cb  = (bf16*)Cout;
    #pragma unroll
    for (int mt = 0; mt < 2; mt++) {
        int row0 = bm + warpM*32 + mt*16 + g;
        int row1 = row0 + 8;
        #pragma unroll
        for (int nt = 0; nt < 8; nt++) {
            int col = bn + warpN*64 + nt*8 + 2*t;
            float b0 = bias[col], b1 = bias[col+1];
            float v00 = acc[mt][nt][0] + b0;
            float v01 = acc[mt][nt][1] + b1;
            float v10 = acc[mt][nt][2] + b0;
            float v11 = acc[mt][nt][3] + b1;
            if (MODE == 1) { v00 *= scale; v01 *= scale; v10 *= scale; v11 *= scale; }
            if (MODE == 2) {
                v00 = 0.5f*v00*(1.0f + erff(v00*0.70710678118654752f));
                v01 = 0.5f*v01*(1.0f + erff(v01*0.70710678118654752f));
                v10 = 0.5f*v10*(1.0f + erff(v10*0.70710678118654752f));
                v11 = 0.5f*v11*(1.0f + erff(v11*0.70710678118654752f));
            }
            if (MODE == 3) {
                float2 r0 = *(const float2*)&res[(size_t)row0*N + col];
                float2 r1 = *(const float2*)&res[(size_t)row1*N + col];
                v00 += r0.x; v01 += r0.y; v10 += r1.x; v11 += r1.y;
            }
            if (OUTBF) {
                bf162 p0 = __float22bfloat162_rn(make_float2(v00, v01));
                bf162 p1 = __float22bfloat162_rn(make_float2(v10, v11));
                *(unsigned*)&Cb[(size_t)row0*N + col] = *(unsigned*)&p0;
                *(unsigned*)&Cb[(size_t)row1*N + col] = *(unsigned*)&p1;
            } else {
                *(float2*)&Cf[(size_t)row0*N + col] = make_float2(v00, v01);
                *(float2*)&Cf[(size_t)row1*N + col] = make_float2(v10, v11);
            }
        }
    }
}

// ---------------------------------------------------------------------------
// Neighborhood attention v2: block = 8x4 query tile, 512 threads (16 warps).
// KV patch 14x10 = 140 tokens staged as bf16. q fp32. Softmax weights kept in
// registers, broadcast via shfl for the V pass. Output bf16.
// ---------------------------------------------------------------------------
#define PR 14
#define PC 10
#define PTOK 140
#define DPAD 40
#define AT_THREADS 512

__global__ __launch_bounds__(AT_THREADS)
void nat_attn2(const float* __restrict__ q,
               const bf16* __restrict__ kv,
               const float* __restrict__ rpb,
               bf16* __restrict__ out)
{
    extern __shared__ char smraw[];
    bf16*  Ks = (bf16*)smraw;                  // [4][140][40]
    bf16*  Vs = Ks + 4*PTOK*DPAD;              // [4][140][40]
    float* qs = (float*)(Vs + 4*PTOK*DPAD);    // [32][128]
    float* rs = qs + 32*128;                   // [676]

    const int blk = blockIdx.x;                // 512 = 4 * 8 * 16
    const int b   = blk >> 7;
    const int rem = blk & 127;
    const int it  = (rem >> 4) << 3;
    const int jt  = (rem & 15) << 2;

    int ip0 = it - 3; if (ip0 < 0) ip0 = 0; if (ip0 > Hh - PR) ip0 = Hh - PR;
    int jp0 = jt - 3; if (jp0 < 0) jp0 = 0; if (jp0 > Ww - PC) jp0 = Ww - PC;

    const int tid  = threadIdx.x;
    const int base = b * (Hh*Ww);

    // stage KV (140 tokens x 256 bf16 = 140*32 uint4)
    const uint4* kv4 = (const uint4*)kv;
    for (int f = tid; f < PTOK*32; f += AT_THREADS) {
        int tok = f >> 5;
        int c8  = f & 31;
        int r   = tok / PC;
        int cc  = tok - r*PC;
        int g   = base + (ip0 + r)*Ww + (jp0 + cc);
        uint4 v = kv4[(size_t)g*32 + c8];
        int c = c8 * 8;
        if (c < Cc) {
            *(uint4*)&Ks[((c>>5)*PTOK + tok)*DPAD + (c & 31)] = v;
        } else {
            int c2 = c - Cc;
            *(uint4*)&Vs[((c2>>5)*PTOK + tok)*DPAD + (c2 & 31)] = v;
        }
    }
    // stage q fp32 (32 queries x 128)
    for (int f = tid; f < 32*32; f += AT_THREADS) {
        int qq = f >> 5, c4 = f & 31;
        int qi = qq >> 2, qj = qq & 3;
        int g = base + (it + qi)*Ww + (jt + qj);
        *(float4*)&qs[qq*Cc + c4*4] = *(const float4*)&q[(size_t)g*Cc + c4*4];
    }
    for (int f = tid; f < 676; f += AT_THREADS) rs[f] = rpb[f];
    __syncthreads();

    const int w    = tid >> 5;
    const int lane = tid & 31;

    #pragma unroll
    for (int s = 0; s < 8; s++) {
        const int task = w*8 + s;            // 0..127
        const int qq = task >> 2;
        const int h  = task & 3;
        const int qi = qq >> 2, qj = qq & 3;
        const int gi = it + qi, gj = jt + qj;
        int i0 = gi - 3; if (i0 < 0) i0 = 0; if (i0 > Hh - Kk) i0 = Hh - Kk;
        int j0 = gj - 3; if (j0 < 0) j0 = 0; if (j0 > Ww - Kk) j0 = Ww - Kk;
        const int ioff = i0 - ip0;
        const int joff = j0 - jp0;

        // q slice (broadcast loads)
        float qf[32];
        #pragma unroll
        for (int u = 0; u < 8; u++) {
            float4 t4 = *(const float4*)&qs[qq*Cc + h*32 + u*4];
            qf[u*4+0] = t4.x; qf[u*4+1] = t4.y; qf[u*4+2] = t4.z; qf[u*4+3] = t4.w;
        }

        // scores: lane handles neighbors lane and lane+32
        float sc[2];
        #pragma unroll
        for (int r = 0; r < 2; r++) {
            int n = r*32 + lane;
            float val = -INFINITY;
            if (n < 49) {
                int ni = n / 7;
                int nj = n - ni*7;
                int lt = (ioff + ni)*PC + joff + nj;
                const uint4* kp = (const uint4*)&Ks[(h*PTOK + lt)*DPAD];
                float a0 = 0.f;
                #pragma unroll
                for (int u = 0; u < 4; u++) {
                    uint4 kk4 = kp[u];
                    float2 f0 = __bfloat1622float2(*(const bf162*)&kk4.x);
                    float2 f1 = __bfloat1622float2(*(const bf162*)&kk4.y);
                    float2 f2 = __bfloat1622float2(*(const bf162*)&kk4.z);
                    float2 f3 = __bfloat1622float2(*(const bf162*)&kk4.w);
                    a0 = fmaf(qf[u*8+0], f0.x, a0);
                    a0 = fmaf(qf[u*8+1], f0.y, a0);
                    a0 = fmaf(qf[u*8+2], f1.x, a0);
                    a0 = fmaf(qf[u*8+3], f1.y, a0);
                    a0 = fmaf(qf[u*8+4], f2.x, a0);
                    a0 = fmaf(qf[u*8+5], f2.y, a0);
                    a0 = fmaf(qf[u*8+6], f3.x, a0);
                    a0 = fmaf(qf[u*8+7], f3.y, a0);
                }
                int ri = i0 + ni - gi + (Kk - 1);
                int rj = j0 + nj - gj + (Kk - 1);
                val = a0 + rs[h*169 + ri*13 + rj];
            }
            sc[r] = val;
        }

        // softmax over 49 within warp
        float mx = fmaxf(sc[0], sc[1]);
        #pragma unroll
        for (int off = 16; off; off >>= 1)
            mx = fmaxf(mx, __shfl_xor_sync(0xffffffff, mx, off));
        float e0 = __expf(sc[0] - mx);
        float e1 = __expf(sc[1] - mx);
        float sum = e0 + e1;
        #pragma unroll
        for (int off = 16; off; off >>= 1)
            sum += __shfl_xor_sync(0xffffffff, sum, off);
        float rinv = 1.0f / sum;
        float p0 = e0 * rinv;
        float p1 = e1 * rinv;

        // V pass: lane = dim, p broadcast via shfl
        float o = 0.0f;
        #pragma unroll
        for (int n = 0; n < 49; n++) {
            float pn = (n < 32) ? __shfl_sync(0xffffffff, p0, n)
                                : __shfl_sync(0xffffffff, p1, n - 32);
            int ni = n / 7;
            int nj = n - ni*7;
            int lt = (ioff + ni)*PC + joff + nj;
            float vv = __bfloat162float(Vs[(h*PTOK + lt)*DPAD + lane]);
            o = fmaf(pn, vv, o);
        }
        int g = base + gi*Ww + gj;
        out[(size_t)g*Cc + h*32 + lane] = __float2bfloat16(o);
    }
}

// ---------------------------------------------------------------------------
// Launch
// ---------------------------------------------------------------------------
extern "C" void kernel_launch(void* const* d_in, const int* in_sizes, int n_in,
                              void* d_out, int out_size)
{
    const float* query     = (const float*)d_in[0];
    const float* key_value = (const float*)d_in[1];
    const float* g1  = (const float*)d_in[2];
    const float* b1  = (const float*)d_in[3];
    const float* g2  = (const float*)d_in[4];
    const float* b2  = (const float*)d_in[5];
    const float* g3  = (const float*)d_in[6];
    const float* b3  = (const float*)d_in[7];
    const float* Wq  = (const float*)d_in[8];
    const float* bq  = (const float*)d_in[9];
    const float* Wkv = (const float*)d_in[10];
    const float* bkv = (const float*)d_in[11];
    const float* Wp  = (const float*)d_in[12];
    const float* bp  = (const float*)d_in[13];
    const float* rpb = (const float*)d_in[14];
    const float* W1  = (const float*)d_in[15];
    const float* bm1 = (const float*)d_in[16];
    const float* W2  = (const float*)d_in[17];
    const float* bm2 = (const float*)d_in[18];
    float* out = (float*)d_out;

    bf16*  qn     = nullptr; cudaGetSymbolAddress((void**)&qn,     g_qn);
    bf16*  kvn    = nullptr; cudaGetSymbolAddress((void**)&kvn,    g_kvn);
    float* qbuf   = nullptr; cudaGetSymbolAddress((void**)&qbuf,   g_q);
    bf16*  kvbuf  = nullptr; cudaGetSymbolAddress((void**)&kvbuf,  g_kv);
    bf16*  attn   = nullptr; cudaGetSymbolAddress((void**)&attn,   g_attn);
    float* xbuf   = nullptr; cudaGetSymbolAddress((void**)&xbuf,   g_x);
    bf16*  hln    = nullptr; cudaGetSymbolAddress((void**)&hln,    g_hln);
    bf16*  hidden = nullptr; cudaGetSymbolAddress((void**)&hidden, g_hidden);

    static bool attr_set = false;
    const int at_smem = (2*4*PTOK*DPAD)*2 + (32*128 + 676)*4;   // 108688 B
    if (!attr_set) {
        cudaFuncSetAttribute(nat_attn2,
                             cudaFuncAttributeMaxDynamicSharedMemorySize, at_smem);
        attr_set = true;
    }

    const int lnBlocks = (NTOK * 32) / 256;

    // 1) LayerNorms -> bf16
    ln_kernel_bf16<<<lnBlocks, 256>>>(query,     g1, b1, qn,  NTOK);
    ln_kernel_bf16<<<lnBlocks, 256>>>(key_value, g2, b2, kvn, NTOK);

    // 2) Q projection (scaled, fp32 out) and KV projection (bf16 out)
    gemm_bf<1,0><<<dim3(Cc/128,   NTOK/64), 128>>>(qn,  Wq,  bq,  nullptr, qbuf,  NTOK, Cc,   Cc, 0.17677669529663689f);
    gemm_bf<0,1><<<dim3(2*Cc/128, NTOK/64), 128>>>(kvn, Wkv, bkv, nullptr, kvbuf, NTOK, 2*Cc, Cc, 1.0f);

    // 3) Neighborhood attention (bf16 KV, bf16 out)
    nat_attn2<<<Bq*(Hh/8)*(Ww/4), AT_THREADS, at_smem>>>(qbuf, kvbuf, rpb, attn);

    // 4) Output projection + residual (fp32 out)
    gemm_bf<3,0><<<dim3(Cc/128, NTOK/64), 128>>>(attn, Wp, bp, key_value, xbuf, NTOK, Cc, Cc, 1.0f);

    // 5) LN3 + MLP
    ln_kernel_bf16<<<lnBlocks, 256>>>(xbuf, g3, b3, hln, NTOK);
    gemm_bf<2,1><<<dim3(MLPD/128, NTOK/64), 128>>>(hln,    W1, bm1, nullptr, hidden, NTOK, MLPD, Cc,   1.0f);
    gemm_bf<3,0><<<dim3(Cc/128,   NTOK/64), 128>>>(hidden, W2, bm2, xbuf,    out,    NTOK, Cc,   MLPD, 1.0f);
}